// round 16
// baseline (speedup 1.0000x reference)
#include <cuda_runtime.h>
#include <cuda_fp16.h>
#include <math.h>
#include <stdint.h>

#define N_NODES 20000
#define HDIM    256
#define H3      768
#define OUT_DIM 128
#define NEDGE   320000
#define TSTEPS  3

// ---------------- scratch (static device globals; no allocs allowed) --------
__device__ float g_h [N_NODES * HDIM];
__device__ float g_as[N_NODES];
__device__ float g_ad[N_NODES];
// fp16 buffers
__device__ __half g_hf [N_NODES * HDIM];
__device__ __half g_xpf[N_NODES * HDIM];
__device__ __half g_gtf[N_NODES * HDIM];
__device__ __half g_gxf[N_NODES * H3];
__device__ __half g_ghf[N_NODES * H3];
__device__ __half g_wgf [HDIM * HDIM];
__device__ __half g_wihf[H3 * HDIM];
__device__ __half g_whhf[H3 * HDIM];
__device__ __half g_lwf [OUT_DIM * HDIM];
// CSR by destination (srcs = source node per sorted-edge slot)
__device__ int g_cnt[N_NODES + 1];
__device__ int g_row[N_NODES + 1];
__device__ int g_cur[N_NODES];
__device__ int g_srcs[NEDGE];

// ---------------- helpers ----------------------------------------------------
__device__ __forceinline__ float sigmf(float x) { return 1.f / (1.f + expf(-x)); }

__device__ __forceinline__ uint32_t smem_u32(const void* p) {
    uint32_t a;
    asm("{ .reg .u64 t; cvta.to.shared.u64 t, %1; cvt.u32.u64 %0, t; }" : "=r"(a) : "l"(p));
    return a;
}
__device__ __forceinline__ uint2 pack4f(float4 v) {
    __half2 h0 = __floats2half2_rn(v.x, v.y);
    __half2 h1 = __floats2half2_rn(v.z, v.w);
    uint2 r;
    r.x = *(uint32_t*)&h0; r.y = *(uint32_t*)&h1;
    return r;
}
__device__ __forceinline__ float4 unpack4h(uint2 u) {
    __half2 a = *(__half2*)&u.x, b = *(__half2*)&u.y;
    float2 fa = __half22float2(a), fb = __half22float2(b);
    return make_float4(fa.x, fa.y, fb.x, fb.y);
}

#define LDSM_X4(r0,r1,r2,r3,addr) \
    asm volatile("ldmatrix.sync.aligned.m8n8.x4.shared.b16 {%0,%1,%2,%3}, [%4];" \
        : "=r"(r0),"=r"(r1),"=r"(r2),"=r"(r3) : "r"(addr))
#define MMA_F16(c0,c1,c2,c3,a0,a1,a2,a3,b0,b1) \
    asm("mma.sync.aligned.m16n8k16.row.col.f32.f16.f16.f32 " \
        "{%0,%1,%2,%3},{%4,%5,%6,%7},{%8,%9},{%0,%1,%2,%3};" \
        : "+f"(c0),"+f"(c1),"+f"(c2),"+f"(c3) \
        : "r"(a0),"r"(a1),"r"(a2),"r"(a3),"r"(b0),"r"(b1))
#define CP_COMMIT()  asm volatile("cp.async.commit_group;" ::: "memory")
#define CP_WAIT0()   asm volatile("cp.async.wait_group 0;" ::: "memory")
#define CP_WAIT1()   asm volatile("cp.async.wait_group 1;" ::: "memory")

// ====== fp16 GEMM: C = A[M,K]*B[N,K]^T + bias ================================
// CTA tile 128x128, 8 warps (2M x 4N), warp tile 64x32 (mt=4, nt=4).
// K chunk 64 -> 128B rows. Stage: A +0 (16KB), B +16384 (16KB); 32KB x 3 stages.
#define GEMM_SMEM (3 * 32768)

extern __shared__ uint32_t smem_dyn[];

__device__ __forceinline__ void gemm_body(
    const __half* __restrict__ A, const __half* __restrict__ B,
    const float* __restrict__ bias, float* __restrict__ C, __half* __restrict__ Cf,
    const float* __restrict__ att_s, const float* __restrict__ att_d,
    float* __restrict__ as_out, float* __restrict__ ad_out,
    int M, int Nn, int K) {
    const int tid = threadIdx.x;
    const int lane = tid & 31, w = tid >> 5;
    const int wm = (w & 1) * 64, wn = (w >> 1) * 32;
    const int m0 = blockIdx.y * 128, n0 = blockIdx.x * 128;
    const uint32_t sb = smem_u32(smem_dyn);

    const int crow = tid >> 3, cch = tid & 7;

    auto cp_stage = [&](uint32_t stg, int kb) {
        #pragma unroll
        for (int i = 0; i < 4; i++) {
            int row = crow + i * 32;
            uint32_t off = (uint32_t)(row * 128 + ((cch ^ (row & 7)) * 16));
            int gr = m0 + row;
            int sz = (gr < M) ? 16 : 0;
            int gra = (gr < M) ? gr : 0;
            const __half* pa = A + (size_t)gra * K + kb + cch * 8;
            asm volatile("cp.async.ca.shared.global [%0], [%1], 16, %2;"
                         :: "r"(stg + off), "l"(pa), "r"(sz));
            const __half* pb = B + (size_t)(n0 + row) * K + kb + cch * 8;
            asm volatile("cp.async.ca.shared.global [%0], [%1], 16;"
                         :: "r"(stg + 16384 + off), "l"(pb));
        }
        CP_COMMIT();
    };

    int tA = lane >> 3, rA = lane & 7;
    int ca = tA >> 1;
    uint32_t a_rowoff[4]; int a_row7[4];
    #pragma unroll
    for (int mt = 0; mt < 4; mt++) {
        int row = wm + mt * 16 + (tA & 1) * 8 + rA;
        a_rowoff[mt] = (uint32_t)(row * 128);
        a_row7[mt] = row & 7;
    }
    int qb = lane >> 3;
    int b_nt_off = qb >> 1;
    int b_kh = qb & 1;
    uint32_t b_rowoff[2]; int b_row7[2];
    #pragma unroll
    for (int p = 0; p < 2; p++) {
        int row = wn + (p * 2 + b_nt_off) * 8 + (lane & 7);
        b_rowoff[p] = (uint32_t)(row * 128);
        b_row7[p] = row & 7;
    }

    float c[4][4][4];
    #pragma unroll
    for (int i = 0; i < 4; i++)
        #pragma unroll
        for (int j = 0; j < 4; j++)
            #pragma unroll
            for (int k = 0; k < 4; k++) c[i][j][k] = 0.f;

    const int S = K / 64;
    cp_stage(sb, 0);
    cp_stage(sb + 32768u, 64);

    for (int ks = 0; ks < S; ks++) {
        if (ks == S - 1) { CP_WAIT0(); } else { CP_WAIT1(); }
        __syncthreads();
        if (ks + 2 < S) cp_stage(sb + (uint32_t)((ks + 2) % 3) * 32768u, (ks + 2) * 64);
        const uint32_t stg = sb + (uint32_t)(ks % 3) * 32768u;

        #pragma unroll
        for (int k16 = 0; k16 < 4; k16++) {
            uint32_t b[4][2], a[4][4];
            #pragma unroll
            for (int p = 0; p < 2; p++) {
                int pc = (2 * k16 + b_kh) ^ b_row7[p];
                uint32_t ad = stg + 16384 + b_rowoff[p] + (uint32_t)(pc * 16);
                LDSM_X4(b[2*p][0], b[2*p][1], b[2*p+1][0], b[2*p+1][1], ad);
            }
            #pragma unroll
            for (int mt = 0; mt < 4; mt++) {
                int pc = (2 * k16 + ca) ^ a_row7[mt];
                uint32_t ad = stg + a_rowoff[mt] + (uint32_t)(pc * 16);
                LDSM_X4(a[mt][0], a[mt][1], a[mt][2], a[mt][3], ad);
            }
            #pragma unroll
            for (int mt = 0; mt < 4; mt++)
                #pragma unroll
                for (int nt = 0; nt < 4; nt++) {
                    float* cc = c[mt][nt];
                    MMA_F16(cc[0], cc[1], cc[2], cc[3],
                            a[mt][0], a[mt][1], a[mt][2], a[mt][3],
                            b[nt][0], b[nt][1]);
                }
        }
    }

    // epilogue
    int g = lane >> 2, tig = lane & 3;
    #pragma unroll
    for (int mt = 0; mt < 4; mt++) {
        int row = m0 + wm + mt * 16 + g;
        #pragma unroll
        for (int nt = 0; nt < 4; nt++) {
            int col = n0 + wn + nt * 8 + 2 * tig;
            float b0 = 0.f, b1 = 0.f;
            if (bias) { b0 = bias[col]; b1 = bias[col + 1]; }
            float v00 = c[mt][nt][0] + b0, v01 = c[mt][nt][1] + b1;
            float v10 = c[mt][nt][2] + b0, v11 = c[mt][nt][3] + b1;
            if (row < M) {
                if (C)  *(float2*)(C + (size_t)row * Nn + col) = make_float2(v00, v01);
                if (Cf) *(__half2*)(Cf + (size_t)row * Nn + col) =
                            __floats2half2_rn(v00, v01);
            }
            if (row + 8 < M) {
                if (C)  *(float2*)(C + (size_t)(row + 8) * Nn + col) = make_float2(v10, v11);
                if (Cf) *(__half2*)(Cf + (size_t)(row + 8) * Nn + col) =
                            __floats2half2_rn(v10, v11);
            }
        }
    }

    // fused alpha dots from fp32 accumulators
    if (as_out) {
        #pragma unroll
        for (int mt = 0; mt < 4; mt++) {
            float ps0 = 0.f, pd0 = 0.f, ps1 = 0.f, pd1 = 0.f;
            #pragma unroll
            for (int nt = 0; nt < 4; nt++) {
                int col = n0 + wn + nt * 8 + 2 * tig;
                float s0 = att_s[col], s1 = att_s[col + 1];
                float d0 = att_d[col], d1 = att_d[col + 1];
                ps0 += c[mt][nt][0] * s0 + c[mt][nt][1] * s1;
                pd0 += c[mt][nt][0] * d0 + c[mt][nt][1] * d1;
                ps1 += c[mt][nt][2] * s0 + c[mt][nt][3] * s1;
                pd1 += c[mt][nt][2] * d0 + c[mt][nt][3] * d1;
            }
            #pragma unroll
            for (int o = 1; o < 4; o <<= 1) {
                ps0 += __shfl_xor_sync(0xffffffffu, ps0, o);
                pd0 += __shfl_xor_sync(0xffffffffu, pd0, o);
                ps1 += __shfl_xor_sync(0xffffffffu, ps1, o);
                pd1 += __shfl_xor_sync(0xffffffffu, pd1, o);
            }
            if (tig == 0) {
                int row = m0 + wm + mt * 16 + g;
                if (row < M) {
                    atomicAdd(&as_out[row], ps0);
                    atomicAdd(&ad_out[row], pd0);
                }
                if (row + 8 < M) {
                    atomicAdd(&as_out[row + 8], ps1);
                    atomicAdd(&ad_out[row + 8], pd1);
                }
            }
        }
    }
}

__global__ void __launch_bounds__(256, 2)
gemm_f16(const __half* __restrict__ A, const __half* __restrict__ B,
         const float* __restrict__ bias, float* __restrict__ C,
         __half* __restrict__ Cf,
         const float* __restrict__ att_s, const float* __restrict__ att_d,
         float* __restrict__ as_out, float* __restrict__ ad_out,
         int M, int Nn, int K) {
    gemm_body(A, B, bias, C, Cf, att_s, att_d, as_out, ad_out, M, Nn, K);
}

__global__ void __launch_bounds__(256, 2)
gemm_f16_dual(const __half* __restrict__ A0, const __half* __restrict__ B0,
              const float* __restrict__ bias0, __half* __restrict__ Cf0,
              const __half* __restrict__ A1, const __half* __restrict__ B1,
              const float* __restrict__ bias1, __half* __restrict__ Cf1,
              int M, int Nn, int K) {
    if (blockIdx.z == 0)
        gemm_body(A0, B0, bias0, nullptr, Cf0, nullptr, nullptr, nullptr, nullptr,
                  M, Nn, K);
    else
        gemm_body(A1, B1, bias1, nullptr, Cf1, nullptr, nullptr, nullptr, nullptr,
                  M, Nn, K);
}

// ---------------- split kernels ------------------------------------------------
#define WG_F4  (HDIM * HDIM / 4)
#define WIH_F4 (H3 * HDIM / 4)
#define LW_F4  (OUT_DIM * HDIM / 4)
#define WTOT_F4 (WG_F4 + 2 * WIH_F4 + LW_F4)

__global__ void k_split_w(const float4* __restrict__ wg, const float4* __restrict__ wih,
                          const float4* __restrict__ whh, const float4* __restrict__ lw,
                          uint2* __restrict__ wgf, uint2* __restrict__ wihf,
                          uint2* __restrict__ whhf, uint2* __restrict__ lwf) {
    int i = blockIdx.x * blockDim.x + threadIdx.x;
    if (i >= WTOT_F4) return;
    const float4* src; uint2* dst; int j;
    if (i < WG_F4) { src = wg; dst = wgf; j = i; }
    else if (i < WG_F4 + WIH_F4) { src = wih; dst = wihf; j = i - WG_F4; }
    else if (i < WG_F4 + 2 * WIH_F4) { src = whh; dst = whhf; j = i - WG_F4 - WIH_F4; }
    else { src = lw; dst = lwf; j = i - WG_F4 - 2 * WIH_F4; }
    dst[j] = pack4f(src[j]);
}

__global__ void k_copy_split(const float4* __restrict__ src, float4* __restrict__ dst,
                             uint2* __restrict__ hf, float* __restrict__ as_,
                             float* __restrict__ ad_, int n4) {
    int i = blockIdx.x * blockDim.x + threadIdx.x;
    if (i >= n4) return;
    float4 v = src[i];
    dst[i] = v;
    hf[i] = pack4f(v);
    if (i < N_NODES) { as_[i] = 0.f; ad_[i] = 0.f; }
}

// ---------------- CSR build (once per call) -----------------------------------
__global__ void k_csr_zero(int* __restrict__ cnt) {
    int i = blockIdx.x * blockDim.x + threadIdx.x;
    if (i <= N_NODES) cnt[i] = 0;
}
__global__ void k_csr_hist(const int* __restrict__ dst, int* __restrict__ cnt) {
    int e = blockIdx.x * blockDim.x + threadIdx.x;
    if (e < NEDGE) atomicAdd(&cnt[dst[e]], 1);
}
__global__ void k_csr_scan(const int* __restrict__ cnt, int* __restrict__ row,
                           int* __restrict__ cur) {
    __shared__ int wsum[32];
    __shared__ int carry_s;
    int t = threadIdx.x, lane = t & 31, wid = t >> 5;
    if (t == 0) carry_s = 0;
    __syncthreads();
    for (int base = 0; base < N_NODES; base += 4096) {
        int i = base + t * 4;
        int4 v = make_int4(0, 0, 0, 0);
        if (i + 3 < N_NODES) v = *(const int4*)(cnt + i);
        else {
            if (i     < N_NODES) v.x = cnt[i];
            if (i + 1 < N_NODES) v.y = cnt[i + 1];
            if (i + 2 < N_NODES) v.z = cnt[i + 2];
            if (i + 3 < N_NODES) v.w = cnt[i + 3];
        }
        int s = v.x + v.y + v.z + v.w;
        int inc = s;
        #pragma unroll
        for (int o = 1; o < 32; o <<= 1) {
            int x = __shfl_up_sync(0xffffffffu, inc, o);
            if (lane >= o) inc += x;
        }
        if (lane == 31) wsum[wid] = inc;
        __syncthreads();
        if (wid == 0) {
            int ws = wsum[lane];
            int winc = ws;
            #pragma unroll
            for (int o = 1; o < 32; o <<= 1) {
                int x = __shfl_up_sync(0xffffffffu, winc, o);
                if (lane >= o) winc += x;
            }
            wsum[lane] = winc - ws;
        }
        __syncthreads();
        int p = carry_s + wsum[wid] + inc - s;
        if (i     < N_NODES) { row[i] = p;     cur[i] = p; }     p += v.x;
        if (i + 1 < N_NODES) { row[i + 1] = p; cur[i + 1] = p; } p += v.y;
        if (i + 2 < N_NODES) { row[i + 2] = p; cur[i + 2] = p; } p += v.z;
        if (i + 3 < N_NODES) { row[i + 3] = p; cur[i + 3] = p; }
        __syncthreads();
        if (t == 1023) carry_s += wsum[31] + inc;
        __syncthreads();
    }
    if (threadIdx.x == 0) row[N_NODES] = carry_s;
}
__global__ void k_csr_fill(const int* __restrict__ src, const int* __restrict__ dst,
                           int* __restrict__ cur, int* __restrict__ srcs) {
    int e = blockIdx.x * blockDim.x + threadIdx.x;
    if (e >= NEDGE) return;
    int slot = atomicAdd(&cur[dst[e]], 1);
    srcs[slot] = src[e];
}

// ---------------- fused softmax + aggregation (block(256) per node) -----------
// Phase 1: block-wide online softmax (m, den) over the node's edges.
// Phase 2: R14-style coef staging + coalesced scalar accumulation.
__global__ void k_agg(const int* __restrict__ row, const int* __restrict__ srcs,
                      const float* __restrict__ as_, const float* __restrict__ ad_,
                      const __half* __restrict__ xpf, const float* __restrict__ bias,
                      __half* __restrict__ gtf) {
    __shared__ float scoef[256];
    __shared__ int ssrc[256];
    __shared__ float wm_[8], ws_[8];
    __shared__ float bm, bs;
    int d = blockIdx.x;
    int t = threadIdx.x, lane = t & 31, w = t >> 5;
    int r0 = row[d], r1 = row[d + 1];
    float ad = ad_[d];

    // phase 1: per-thread online softmax over strided edges
    float m = -1e30f, s = 0.f;
    for (int i = r0 + t; i < r1; i += 256) {
        float a = as_[srcs[i]] + ad;
        a = (a > 0.f) ? a : 0.01f * a;
        float nm = fmaxf(m, a);
        s = s * expf(m - nm) + expf(a - nm);
        m = nm;
    }
    #pragma unroll
    for (int o = 16; o; o >>= 1) {
        float mo = __shfl_xor_sync(0xffffffffu, m, o);
        float so = __shfl_xor_sync(0xffffffffu, s, o);
        float nm = fmaxf(m, mo);
        s = s * expf(m - nm) + so * expf(mo - nm);
        m = nm;
    }
    if (lane == 0) { wm_[w] = m; ws_[w] = s; }
    __syncthreads();
    if (t == 0) {
        float cm = wm_[0], cs = ws_[0];
        #pragma unroll
        for (int k = 1; k < 8; k++) {
            float mo = wm_[k], so = ws_[k];
            float nm = fmaxf(cm, mo);
            cs = cs * expf(cm - nm) + so * expf(mo - nm);
            cm = nm;
        }
        bm = cm; bs = cs;
    }
    __syncthreads();
    m = bm;
    float inv_den = 1.f / fmaxf(bs, 1e-16f);

    // phase 2: stage coefs, accumulate (as_ values are L1-hot from phase 1)
    float acc = 0.f;
    for (int base = r0; base < r1; base += 256) {
        int n = min(256, r1 - base);
        __syncthreads();
        if (t < n) {
            int sc = srcs[base + t];
            float a = as_[sc] + ad;
            a = (a > 0.f) ? a : 0.01f * a;
            scoef[t] = expf(a - m) * inv_den;
            ssrc[t] = sc;
        }
        __syncthreads();
        for (int i = 0; i < n; i++)
            acc += scoef[i] * __half2float(xpf[(size_t)ssrc[i] * HDIM + t]);
    }
    float v = acc + bias[t];
    v = (v > 0.f) ? v : expm1f(v);
    gtf[(size_t)d * HDIM + t] = __float2half(v);
}

// GRU elementwise; also zeroes alpha accumulators for the next timestep
__global__ void k_gru(const uint2* __restrict__ gxf, const uint2* __restrict__ ghf,
                      float4* __restrict__ h, uint2* __restrict__ hf,
                      float* __restrict__ as_, float* __restrict__ ad_) {
    int idx = blockIdx.x * blockDim.x + threadIdx.x;
    if (idx >= N_NODES * (HDIM / 4)) return;
    if (idx < N_NODES) { as_[idx] = 0.f; ad_[idx] = 0.f; }
    int i = idx >> 6, j = idx & 63;
    int base = i * (H3 / 4);
    float4 xr = unpack4h(gxf[base + j]);
    float4 xz = unpack4h(gxf[base + 64 + j]);
    float4 xn = unpack4h(gxf[base + 128 + j]);
    float4 hr = unpack4h(ghf[base + j]);
    float4 hz = unpack4h(ghf[base + 64 + j]);
    float4 hn = unpack4h(ghf[base + 128 + j]);
    float4 hv = h[idx];
    float4 res;
    { float r = sigmf(xr.x + hr.x), z = sigmf(xz.x + hz.x);
      float n = tanhf(xn.x + r * hn.x); res.x = (1.f - z) * n + z * hv.x; }
    { float r = sigmf(xr.y + hr.y), z = sigmf(xz.y + hz.y);
      float n = tanhf(xn.y + r * hn.y); res.y = (1.f - z) * n + z * hv.y; }
    { float r = sigmf(xr.z + hr.z), z = sigmf(xz.z + hz.z);
      float n = tanhf(xn.z + r * hn.z); res.z = (1.f - z) * n + z * hv.z; }
    { float r = sigmf(xr.w + hr.w), z = sigmf(xz.w + hz.w);
      float n = tanhf(xn.w + r * hn.w); res.w = (1.f - z) * n + z * hv.w; }
    h[idx] = res;
    hf[idx] = pack4f(res);
}

// ---------------- launch ------------------------------------------------------
extern "C" void kernel_launch(void* const* d_in, const int* in_sizes, int n_in,
                              void* d_out, int out_size) {
    const float* x_clique = (const float*)d_in[0];
    const float* W_gat    = (const float*)d_in[1];
    const float* att_src  = (const float*)d_in[2];
    const float* att_dst  = (const float*)d_in[3];
    const float* gat_bias = (const float*)d_in[4];
    const float* W_ih     = (const float*)d_in[5];
    const float* W_hh     = (const float*)d_in[6];
    const float* b_ih     = (const float*)d_in[7];
    const float* b_hh     = (const float*)d_in[8];
    const float* lin_W    = (const float*)d_in[9];
    const float* lin_b    = (const float*)d_in[10];
    const int*   edge     = (const int*)d_in[14];   // int32 (JAX x64 disabled)
    float* out = (float*)d_out;

    const int* e_src = edge;
    const int* e_dst = edge + NEDGE;

    float *h, *as_, *ad_;
    int *cnt, *row, *cur, *srcs;
    __half *hf, *xpf, *gtf, *gxf, *ghf, *wgf, *wihf, *whhf, *lwf;
    cudaGetSymbolAddress((void**)&h,    g_h);
    cudaGetSymbolAddress((void**)&as_,  g_as);
    cudaGetSymbolAddress((void**)&ad_,  g_ad);
    cudaGetSymbolAddress((void**)&cnt,  g_cnt);
    cudaGetSymbolAddress((void**)&row,  g_row);
    cudaGetSymbolAddress((void**)&cur,  g_cur);
    cudaGetSymbolAddress((void**)&srcs, g_srcs);
    cudaGetSymbolAddress((void**)&hf,   g_hf);
    cudaGetSymbolAddress((void**)&xpf,  g_xpf);
    cudaGetSymbolAddress((void**)&gtf,  g_gtf);
    cudaGetSymbolAddress((void**)&gxf,  g_gxf);
    cudaGetSymbolAddress((void**)&ghf,  g_ghf);
    cudaGetSymbolAddress((void**)&wgf,  g_wgf);
    cudaGetSymbolAddress((void**)&wihf, g_wihf);
    cudaGetSymbolAddress((void**)&whhf, g_whhf);
    cudaGetSymbolAddress((void**)&lwf,  g_lwf);

    static int smem_set = 0;
    if (!smem_set) {
        cudaFuncSetAttribute(gemm_f16, cudaFuncAttributeMaxDynamicSharedMemorySize,
                             GEMM_SMEM);
        cudaFuncSetAttribute(gemm_f16_dual, cudaFuncAttributeMaxDynamicSharedMemorySize,
                             GEMM_SMEM);
        smem_set = 1;
    }

    const int NH4   = N_NODES * (HDIM / 4);
    const int B_NH4 = (NH4 + 255) / 256;
    const int B_E   = (NEDGE + 255) / 256;
    const int MT    = (N_NODES + 127) / 128;          // 157 M tiles (128 rows)

    // launch order puts the first GEMM at launch index 3 (ncu profiles it)
    k_split_w<<<(WTOT_F4 + 255) / 256, 256>>>(
        (const float4*)W_gat, (const float4*)W_ih, (const float4*)W_hh,
        (const float4*)lin_W,
        (uint2*)wgf, (uint2*)wihf, (uint2*)whhf, (uint2*)lwf);
    k_copy_split<<<B_NH4, 256>>>((const float4*)x_clique, (float4*)h, (uint2*)hf,
                                 as_, ad_, NH4);
    k_csr_zero<<<(N_NODES + 256) / 256, 256>>>(cnt);
    gemm_f16<<<dim3(HDIM / 128, MT), 256, GEMM_SMEM>>>(            // ts=0 xp GEMM
        hf, wgf, nullptr, nullptr, xpf, att_src, att_dst, as_, ad_,
        N_NODES, HDIM, HDIM);
    k_csr_hist<<<B_E, 256>>>(e_dst, cnt);
    k_csr_scan<<<1, 1024>>>(cnt, row, cur);
    k_csr_fill<<<B_E, 256>>>(e_src, e_dst, cur, srcs);

    for (int ts = 0; ts < TSTEPS; ++ts) {
        if (ts > 0)
            gemm_f16<<<dim3(HDIM / 128, MT), 256, GEMM_SMEM>>>(
                hf, wgf, nullptr, nullptr, xpf, att_src, att_dst, as_, ad_,
                N_NODES, HDIM, HDIM);
        k_agg<<<N_NODES, HDIM>>>(row, srcs, as_, ad_, xpf, gat_bias, gtf);
        gemm_f16_dual<<<dim3(H3 / 128, MT, 2), 256, GEMM_SMEM>>>(
            gtf, wihf, b_ih, gxf,
            hf, whhf, b_hh, ghf,
            N_NODES, H3, HDIM);
        k_gru<<<B_NH4, 256>>>((const uint2*)gxf, (const uint2*)ghf, (float4*)h,
                              (uint2*)hf, as_, ad_);
    }

    gemm_f16<<<dim3(OUT_DIM / 128, MT), 256, GEMM_SMEM>>>(
        hf, lwf, lin_b, out, nullptr, nullptr, nullptr, nullptr, nullptr,
        N_NODES, OUT_DIM, HDIM);
}

// round 17
// speedup vs baseline: 1.1995x; 1.1995x over previous
#include <cuda_runtime.h>
#include <cuda_fp16.h>
#include <math.h>
#include <stdint.h>

#define N_NODES 20000
#define HDIM    256
#define H3      768
#define OUT_DIM 128
#define NEDGE   320000
#define TSTEPS  3

// ---------------- scratch (static device globals; no allocs allowed) --------
__device__ float g_h [N_NODES * HDIM];
__device__ float g_as[N_NODES];
__device__ float g_ad[N_NODES];
__device__ float g_m [N_NODES];
__device__ float g_den[N_NODES];
// fp16 buffers
__device__ __half g_hf [N_NODES * HDIM];
__device__ __half g_xpf[N_NODES * HDIM];
__device__ __half g_gtf[N_NODES * HDIM];
__device__ __half g_gxf[N_NODES * H3];
__device__ __half g_ghf[N_NODES * H3];
__device__ __half g_wgf [HDIM * HDIM];
__device__ __half g_wihf[H3 * HDIM];
__device__ __half g_whhf[H3 * HDIM];
__device__ __half g_lwf [OUT_DIM * HDIM];
// CSR by destination (srcs = source node id per sorted-edge slot)
__device__ int g_cnt[N_NODES + 1];
__device__ int g_row[N_NODES + 1];
__device__ int g_cur[N_NODES];
__device__ int g_srcs[NEDGE];

// ---------------- helpers ----------------------------------------------------
__device__ __forceinline__ float sigmf(float x) { return 1.f / (1.f + expf(-x)); }

__device__ __forceinline__ uint32_t smem_u32(const void* p) {
    uint32_t a;
    asm("{ .reg .u64 t; cvta.to.shared.u64 t, %1; cvt.u32.u64 %0, t; }" : "=r"(a) : "l"(p));
    return a;
}
__device__ __forceinline__ uint2 pack4f(float4 v) {
    __half2 h0 = __floats2half2_rn(v.x, v.y);
    __half2 h1 = __floats2half2_rn(v.z, v.w);
    uint2 r;
    r.x = *(uint32_t*)&h0; r.y = *(uint32_t*)&h1;
    return r;
}
__device__ __forceinline__ float4 unpack4h(uint2 u) {
    __half2 a = *(__half2*)&u.x, b = *(__half2*)&u.y;
    float2 fa = __half22float2(a), fb = __half22float2(b);
    return make_float4(fa.x, fa.y, fb.x, fb.y);
}

#define LDSM_X4(r0,r1,r2,r3,addr) \
    asm volatile("ldmatrix.sync.aligned.m8n8.x4.shared.b16 {%0,%1,%2,%3}, [%4];" \
        : "=r"(r0),"=r"(r1),"=r"(r2),"=r"(r3) : "r"(addr))
#define MMA_F16(c0,c1,c2,c3,a0,a1,a2,a3,b0,b1) \
    asm("mma.sync.aligned.m16n8k16.row.col.f32.f16.f16.f32 " \
        "{%0,%1,%2,%3},{%4,%5,%6,%7},{%8,%9},{%0,%1,%2,%3};" \
        : "+f"(c0),"+f"(c1),"+f"(c2),"+f"(c3) \
        : "r"(a0),"r"(a1),"r"(a2),"r"(a3),"r"(b0),"r"(b1))
#define CP_COMMIT()  asm volatile("cp.async.commit_group;" ::: "memory")
#define CP_WAIT0()   asm volatile("cp.async.wait_group 0;" ::: "memory")
#define CP_WAIT1()   asm volatile("cp.async.wait_group 1;" ::: "memory")

// ====== fp16 GEMM: C = A[M,K]*B[N,K]^T + bias ================================
// CTA tile 128x128, 8 warps (2M x 4N), warp tile 64x32 (mt=4, nt=4).
// K chunk 64 -> 128B rows. Stage: A +0 (16KB), B +16384 (16KB); 32KB x 3 stages.
#define GEMM_SMEM (3 * 32768)

extern __shared__ uint32_t smem_dyn[];

__device__ __forceinline__ void gemm_body(
    const __half* __restrict__ A, const __half* __restrict__ B,
    const float* __restrict__ bias, float* __restrict__ C, __half* __restrict__ Cf,
    const float* __restrict__ att_s, const float* __restrict__ att_d,
    float* __restrict__ as_out, float* __restrict__ ad_out,
    int M, int Nn, int K) {
    const int tid = threadIdx.x;
    const int lane = tid & 31, w = tid >> 5;
    const int wm = (w & 1) * 64, wn = (w >> 1) * 32;
    const int m0 = blockIdx.y * 128, n0 = blockIdx.x * 128;
    const uint32_t sb = smem_u32(smem_dyn);

    const int crow = tid >> 3, cch = tid & 7;

    auto cp_stage = [&](uint32_t stg, int kb) {
        #pragma unroll
        for (int i = 0; i < 4; i++) {
            int row = crow + i * 32;
            uint32_t off = (uint32_t)(row * 128 + ((cch ^ (row & 7)) * 16));
            int gr = m0 + row;
            int sz = (gr < M) ? 16 : 0;
            int gra = (gr < M) ? gr : 0;
            const __half* pa = A + (size_t)gra * K + kb + cch * 8;
            asm volatile("cp.async.ca.shared.global [%0], [%1], 16, %2;"
                         :: "r"(stg + off), "l"(pa), "r"(sz));
            const __half* pb = B + (size_t)(n0 + row) * K + kb + cch * 8;
            asm volatile("cp.async.ca.shared.global [%0], [%1], 16;"
                         :: "r"(stg + 16384 + off), "l"(pb));
        }
        CP_COMMIT();
    };

    int tA = lane >> 3, rA = lane & 7;
    int ca = tA >> 1;
    uint32_t a_rowoff[4]; int a_row7[4];
    #pragma unroll
    for (int mt = 0; mt < 4; mt++) {
        int row = wm + mt * 16 + (tA & 1) * 8 + rA;
        a_rowoff[mt] = (uint32_t)(row * 128);
        a_row7[mt] = row & 7;
    }
    int qb = lane >> 3;
    int b_nt_off = qb >> 1;
    int b_kh = qb & 1;
    uint32_t b_rowoff[2]; int b_row7[2];
    #pragma unroll
    for (int p = 0; p < 2; p++) {
        int row = wn + (p * 2 + b_nt_off) * 8 + (lane & 7);
        b_rowoff[p] = (uint32_t)(row * 128);
        b_row7[p] = row & 7;
    }

    float c[4][4][4];
    #pragma unroll
    for (int i = 0; i < 4; i++)
        #pragma unroll
        for (int j = 0; j < 4; j++)
            #pragma unroll
            for (int k = 0; k < 4; k++) c[i][j][k] = 0.f;

    const int S = K / 64;
    cp_stage(sb, 0);
    cp_stage(sb + 32768u, 64);

    for (int ks = 0; ks < S; ks++) {
        if (ks == S - 1) { CP_WAIT0(); } else { CP_WAIT1(); }
        __syncthreads();
        if (ks + 2 < S) cp_stage(sb + (uint32_t)((ks + 2) % 3) * 32768u, (ks + 2) * 64);
        const uint32_t stg = sb + (uint32_t)(ks % 3) * 32768u;

        #pragma unroll
        for (int k16 = 0; k16 < 4; k16++) {
            uint32_t b[4][2], a[4][4];
            #pragma unroll
            for (int p = 0; p < 2; p++) {
                int pc = (2 * k16 + b_kh) ^ b_row7[p];
                uint32_t ad = stg + 16384 + b_rowoff[p] + (uint32_t)(pc * 16);
                LDSM_X4(b[2*p][0], b[2*p][1], b[2*p+1][0], b[2*p+1][1], ad);
            }
            #pragma unroll
            for (int mt = 0; mt < 4; mt++) {
                int pc = (2 * k16 + ca) ^ a_row7[mt];
                uint32_t ad = stg + a_rowoff[mt] + (uint32_t)(pc * 16);
                LDSM_X4(a[mt][0], a[mt][1], a[mt][2], a[mt][3], ad);
            }
            #pragma unroll
            for (int mt = 0; mt < 4; mt++)
                #pragma unroll
                for (int nt = 0; nt < 4; nt++) {
                    float* cc = c[mt][nt];
                    MMA_F16(cc[0], cc[1], cc[2], cc[3],
                            a[mt][0], a[mt][1], a[mt][2], a[mt][3],
                            b[nt][0], b[nt][1]);
                }
        }
    }

    // epilogue
    int g = lane >> 2, tig = lane & 3;
    #pragma unroll
    for (int mt = 0; mt < 4; mt++) {
        int row = m0 + wm + mt * 16 + g;
        #pragma unroll
        for (int nt = 0; nt < 4; nt++) {
            int col = n0 + wn + nt * 8 + 2 * tig;
            float b0 = 0.f, b1 = 0.f;
            if (bias) { b0 = bias[col]; b1 = bias[col + 1]; }
            float v00 = c[mt][nt][0] + b0, v01 = c[mt][nt][1] + b1;
            float v10 = c[mt][nt][2] + b0, v11 = c[mt][nt][3] + b1;
            if (row < M) {
                if (C)  *(float2*)(C + (size_t)row * Nn + col) = make_float2(v00, v01);
                if (Cf) *(__half2*)(Cf + (size_t)row * Nn + col) =
                            __floats2half2_rn(v00, v01);
            }
            if (row + 8 < M) {
                if (C)  *(float2*)(C + (size_t)(row + 8) * Nn + col) = make_float2(v10, v11);
                if (Cf) *(__half2*)(Cf + (size_t)(row + 8) * Nn + col) =
                            __floats2half2_rn(v10, v11);
            }
        }
    }

    // fused alpha dots from fp32 accumulators
    if (as_out) {
        #pragma unroll
        for (int mt = 0; mt < 4; mt++) {
            float ps0 = 0.f, pd0 = 0.f, ps1 = 0.f, pd1 = 0.f;
            #pragma unroll
            for (int nt = 0; nt < 4; nt++) {
                int col = n0 + wn + nt * 8 + 2 * tig;
                float s0 = att_s[col], s1 = att_s[col + 1];
                float d0 = att_d[col], d1 = att_d[col + 1];
                ps0 += c[mt][nt][0] * s0 + c[mt][nt][1] * s1;
                pd0 += c[mt][nt][0] * d0 + c[mt][nt][1] * d1;
                ps1 += c[mt][nt][2] * s0 + c[mt][nt][3] * s1;
                pd1 += c[mt][nt][2] * d0 + c[mt][nt][3] * d1;
            }
            #pragma unroll
            for (int o = 1; o < 4; o <<= 1) {
                ps0 += __shfl_xor_sync(0xffffffffu, ps0, o);
                pd0 += __shfl_xor_sync(0xffffffffu, pd0, o);
                ps1 += __shfl_xor_sync(0xffffffffu, ps1, o);
                pd1 += __shfl_xor_sync(0xffffffffu, pd1, o);
            }
            if (tig == 0) {
                int row = m0 + wm + mt * 16 + g;
                if (row < M) {
                    atomicAdd(&as_out[row], ps0);
                    atomicAdd(&ad_out[row], pd0);
                }
                if (row + 8 < M) {
                    atomicAdd(&as_out[row + 8], ps1);
                    atomicAdd(&ad_out[row + 8], pd1);
                }
            }
        }
    }
}

__global__ void __launch_bounds__(256, 2)
gemm_f16(const __half* __restrict__ A, const __half* __restrict__ B,
         const float* __restrict__ bias, float* __restrict__ C,
         __half* __restrict__ Cf,
         const float* __restrict__ att_s, const float* __restrict__ att_d,
         float* __restrict__ as_out, float* __restrict__ ad_out,
         int M, int Nn, int K) {
    gemm_body(A, B, bias, C, Cf, att_s, att_d, as_out, ad_out, M, Nn, K);
}

__global__ void __launch_bounds__(256, 2)
gemm_f16_dual(const __half* __restrict__ A0, const __half* __restrict__ B0,
              const float* __restrict__ bias0, __half* __restrict__ Cf0,
              const __half* __restrict__ A1, const __half* __restrict__ B1,
              const float* __restrict__ bias1, __half* __restrict__ Cf1,
              int M, int Nn, int K) {
    if (blockIdx.z == 0)
        gemm_body(A0, B0, bias0, nullptr, Cf0, nullptr, nullptr, nullptr, nullptr,
                  M, Nn, K);
    else
        gemm_body(A1, B1, bias1, nullptr, Cf1, nullptr, nullptr, nullptr, nullptr,
                  M, Nn, K);
}

// ---------------- split kernels ------------------------------------------------
#define WG_F4  (HDIM * HDIM / 4)
#define WIH_F4 (H3 * HDIM / 4)
#define LW_F4  (OUT_DIM * HDIM / 4)
#define WTOT_F4 (WG_F4 + 2 * WIH_F4 + LW_F4)

__global__ void k_split_w(const float4* __restrict__ wg, const float4* __restrict__ wih,
                          const float4* __restrict__ whh, const float4* __restrict__ lw,
                          uint2* __restrict__ wgf, uint2* __restrict__ wihf,
                          uint2* __restrict__ whhf, uint2* __restrict__ lwf) {
    int i = blockIdx.x * blockDim.x + threadIdx.x;
    if (i >= WTOT_F4) return;
    const float4* src; uint2* dst; int j;
    if (i < WG_F4) { src = wg; dst = wgf; j = i; }
    else if (i < WG_F4 + WIH_F4) { src = wih; dst = wihf; j = i - WG_F4; }
    else if (i < WG_F4 + 2 * WIH_F4) { src = whh; dst = whhf; j = i - WG_F4 - WIH_F4; }
    else { src = lw; dst = lwf; j = i - WG_F4 - 2 * WIH_F4; }
    dst[j] = pack4f(src[j]);
}

__global__ void k_copy_split(const float4* __restrict__ src, float4* __restrict__ dst,
                             uint2* __restrict__ hf, float* __restrict__ as_,
                             float* __restrict__ ad_, int n4) {
    int i = blockIdx.x * blockDim.x + threadIdx.x;
    if (i >= n4) return;
    float4 v = src[i];
    dst[i] = v;
    hf[i] = pack4f(v);
    if (i < N_NODES) { as_[i] = 0.f; ad_[i] = 0.f; }
}

// ---------------- CSR build (once per call) -----------------------------------
__global__ void k_csr_zero(int* __restrict__ cnt) {
    int i = blockIdx.x * blockDim.x + threadIdx.x;
    if (i <= N_NODES) cnt[i] = 0;
}
__global__ void k_csr_hist(const int* __restrict__ dst, int* __restrict__ cnt) {
    int e = blockIdx.x * blockDim.x + threadIdx.x;
    if (e < NEDGE) atomicAdd(&cnt[dst[e]], 1);
}
__global__ void k_csr_scan(const int* __restrict__ cnt, int* __restrict__ row,
                           int* __restrict__ cur) {
    __shared__ int wsum[32];
    __shared__ int carry_s;
    int t = threadIdx.x, lane = t & 31, wid = t >> 5;
    if (t == 0) carry_s = 0;
    __syncthreads();
    for (int base = 0; base < N_NODES; base += 4096) {
        int i = base + t * 4;
        int4 v = make_int4(0, 0, 0, 0);
        if (i + 3 < N_NODES) v = *(const int4*)(cnt + i);
        else {
            if (i     < N_NODES) v.x = cnt[i];
            if (i + 1 < N_NODES) v.y = cnt[i + 1];
            if (i + 2 < N_NODES) v.z = cnt[i + 2];
            if (i + 3 < N_NODES) v.w = cnt[i + 3];
        }
        int s = v.x + v.y + v.z + v.w;
        int inc = s;
        #pragma unroll
        for (int o = 1; o < 32; o <<= 1) {
            int x = __shfl_up_sync(0xffffffffu, inc, o);
            if (lane >= o) inc += x;
        }
        if (lane == 31) wsum[wid] = inc;
        __syncthreads();
        if (wid == 0) {
            int ws = wsum[lane];
            int winc = ws;
            #pragma unroll
            for (int o = 1; o < 32; o <<= 1) {
                int x = __shfl_up_sync(0xffffffffu, winc, o);
                if (lane >= o) winc += x;
            }
            wsum[lane] = winc - ws;
        }
        __syncthreads();
        int p = carry_s + wsum[wid] + inc - s;
        if (i     < N_NODES) { row[i] = p;     cur[i] = p; }     p += v.x;
        if (i + 1 < N_NODES) { row[i + 1] = p; cur[i + 1] = p; } p += v.y;
        if (i + 2 < N_NODES) { row[i + 2] = p; cur[i + 2] = p; } p += v.z;
        if (i + 3 < N_NODES) { row[i + 3] = p; cur[i + 3] = p; }
        __syncthreads();
        if (t == 1023) carry_s += wsum[31] + inc;
        __syncthreads();
    }
    if (threadIdx.x == 0) row[N_NODES] = carry_s;
}
// fill: store the SOURCE node id per sorted slot (no eid indirection)
__global__ void k_csr_fill(const int* __restrict__ src, const int* __restrict__ dst,
                           int* __restrict__ cur, int* __restrict__ srcs) {
    int e = blockIdx.x * blockDim.x + threadIdx.x;
    if (e >= NEDGE) return;
    int slot = atomicAdd(&cur[dst[e]], 1);
    srcs[slot] = src[e];
}

// ---------------- per-timestep edge/node kernels ------------------------------
__global__ void k_node_ms(const int* __restrict__ row, const int* __restrict__ srcs,
                          const float* __restrict__ as_, const float* __restrict__ ad_,
                          float* __restrict__ mm, float* __restrict__ den) {
    int node = (blockIdx.x * blockDim.x + threadIdx.x) >> 5;
    int lane = threadIdx.x & 31;
    if (node >= N_NODES) return;
    int r0 = row[node], r1 = row[node + 1];
    float ad = ad_[node];
    float m = -1e30f, s = 0.f;
    for (int i = r0 + lane; i < r1; i += 32) {
        float a = as_[srcs[i]] + ad;
        a = (a > 0.f) ? a : 0.01f * a;
        float nm = fmaxf(m, a);
        s = s * expf(m - nm) + expf(a - nm);
        m = nm;
    }
    #pragma unroll
    for (int o = 16; o; o >>= 1) {
        float mo = __shfl_xor_sync(0xffffffffu, m, o);
        float so = __shfl_xor_sync(0xffffffffu, s, o);
        float nm = fmaxf(m, mo);
        s = s * expf(m - nm) + so * expf(mo - nm);
        m = nm;
    }
    if (lane == 0) { mm[node] = m; den[node] = s; }
}

// block(128) per node: coef staging + __half2 coalesced accumulation
__global__ void k_agg(const int* __restrict__ row, const int* __restrict__ srcs,
                      const float* __restrict__ as_, const float* __restrict__ ad_,
                      const float* __restrict__ mm, const float* __restrict__ den,
                      const __half2* __restrict__ xpf2, const float* __restrict__ bias,
                      __half2* __restrict__ gtf2) {
    __shared__ float scoef[128];
    __shared__ int ssrc[128];
    int d = blockIdx.x;
    int t = threadIdx.x;                 // 0..127, covers half2 column pairs
    int r0 = row[d], r1 = row[d + 1];
    float ad = ad_[d], m = mm[d];
    float inv_den = 1.f / fmaxf(den[d], 1e-16f);
    float ax = 0.f, ay = 0.f;
    for (int base = r0; base < r1; base += 128) {
        int n = min(128, r1 - base);
        __syncthreads();
        if (t < n) {
            int sc = srcs[base + t];
            float a = as_[sc] + ad;
            a = (a > 0.f) ? a : 0.01f * a;
            scoef[t] = expf(a - m) * inv_den;
            ssrc[t] = sc;
        }
        __syncthreads();
        for (int i = 0; i < n; i++) {
            float cf = scoef[i];
            float2 f = __half22float2(xpf2[(size_t)ssrc[i] * (HDIM / 2) + t]);
            ax += cf * f.x;
            ay += cf * f.y;
        }
    }
    float vx = ax + bias[2 * t];
    float vy = ay + bias[2 * t + 1];
    vx = (vx > 0.f) ? vx : expm1f(vx);
    vy = (vy > 0.f) ? vy : expm1f(vy);
    gtf2[(size_t)d * (HDIM / 2) + t] = __floats2half2_rn(vx, vy);
}

// GRU elementwise; also zeroes alpha accumulators for the next timestep
__global__ void k_gru(const uint2* __restrict__ gxf, const uint2* __restrict__ ghf,
                      float4* __restrict__ h, uint2* __restrict__ hf,
                      float* __restrict__ as_, float* __restrict__ ad_) {
    int idx = blockIdx.x * blockDim.x + threadIdx.x;
    if (idx >= N_NODES * (HDIM / 4)) return;
    if (idx < N_NODES) { as_[idx] = 0.f; ad_[idx] = 0.f; }
    int i = idx >> 6, j = idx & 63;
    int base = i * (H3 / 4);
    float4 xr = unpack4h(gxf[base + j]);
    float4 xz = unpack4h(gxf[base + 64 + j]);
    float4 xn = unpack4h(gxf[base + 128 + j]);
    float4 hr = unpack4h(ghf[base + j]);
    float4 hz = unpack4h(ghf[base + 64 + j]);
    float4 hn = unpack4h(ghf[base + 128 + j]);
    float4 hv = h[idx];
    float4 res;
    { float r = sigmf(xr.x + hr.x), z = sigmf(xz.x + hz.x);
      float n = tanhf(xn.x + r * hn.x); res.x = (1.f - z) * n + z * hv.x; }
    { float r = sigmf(xr.y + hr.y), z = sigmf(xz.y + hz.y);
      float n = tanhf(xn.y + r * hn.y); res.y = (1.f - z) * n + z * hv.y; }
    { float r = sigmf(xr.z + hr.z), z = sigmf(xz.z + hz.z);
      float n = tanhf(xn.z + r * hn.z); res.z = (1.f - z) * n + z * hv.z; }
    { float r = sigmf(xr.w + hr.w), z = sigmf(xz.w + hz.w);
      float n = tanhf(xn.w + r * hn.w); res.w = (1.f - z) * n + z * hv.w; }
    h[idx] = res;
    hf[idx] = pack4f(res);
}

// ---------------- launch ------------------------------------------------------
extern "C" void kernel_launch(void* const* d_in, const int* in_sizes, int n_in,
                              void* d_out, int out_size) {
    const float* x_clique = (const float*)d_in[0];
    const float* W_gat    = (const float*)d_in[1];
    const float* att_src  = (const float*)d_in[2];
    const float* att_dst  = (const float*)d_in[3];
    const float* gat_bias = (const float*)d_in[4];
    const float* W_ih     = (const float*)d_in[5];
    const float* W_hh     = (const float*)d_in[6];
    const float* b_ih     = (const float*)d_in[7];
    const float* b_hh     = (const float*)d_in[8];
    const float* lin_W    = (const float*)d_in[9];
    const float* lin_b    = (const float*)d_in[10];
    const int*   edge     = (const int*)d_in[14];   // int32 (JAX x64 disabled)
    float* out = (float*)d_out;

    const int* e_src = edge;
    const int* e_dst = edge + NEDGE;

    float *h, *as_, *ad_, *mm, *den;
    int *cnt, *row, *cur, *srcs;
    __half *hf, *xpf, *gtf, *gxf, *ghf, *wgf, *wihf, *whhf, *lwf;
    cudaGetSymbolAddress((void**)&h,    g_h);
    cudaGetSymbolAddress((void**)&as_,  g_as);
    cudaGetSymbolAddress((void**)&ad_,  g_ad);
    cudaGetSymbolAddress((void**)&mm,   g_m);
    cudaGetSymbolAddress((void**)&den,  g_den);
    cudaGetSymbolAddress((void**)&cnt,  g_cnt);
    cudaGetSymbolAddress((void**)&row,  g_row);
    cudaGetSymbolAddress((void**)&cur,  g_cur);
    cudaGetSymbolAddress((void**)&srcs, g_srcs);
    cudaGetSymbolAddress((void**)&hf,   g_hf);
    cudaGetSymbolAddress((void**)&xpf,  g_xpf);
    cudaGetSymbolAddress((void**)&gtf,  g_gtf);
    cudaGetSymbolAddress((void**)&gxf,  g_gxf);
    cudaGetSymbolAddress((void**)&ghf,  g_ghf);
    cudaGetSymbolAddress((void**)&wgf,  g_wgf);
    cudaGetSymbolAddress((void**)&wihf, g_wihf);
    cudaGetSymbolAddress((void**)&whhf, g_whhf);
    cudaGetSymbolAddress((void**)&lwf,  g_lwf);

    static int smem_set = 0;
    if (!smem_set) {
        cudaFuncSetAttribute(gemm_f16, cudaFuncAttributeMaxDynamicSharedMemorySize,
                             GEMM_SMEM);
        cudaFuncSetAttribute(gemm_f16_dual, cudaFuncAttributeMaxDynamicSharedMemorySize,
                             GEMM_SMEM);
        smem_set = 1;
    }

    const int NH4   = N_NODES * (HDIM / 4);
    const int B_NH4 = (NH4 + 255) / 256;
    const int B_E   = (NEDGE + 255) / 256;
    const int B_W   = (N_NODES * 32 + 255) / 256;
    const int MT    = (N_NODES + 127) / 128;          // 157 M tiles (128 rows)

    // launch order puts the first GEMM at launch index 3 (ncu profiles it)
    k_split_w<<<(WTOT_F4 + 255) / 256, 256>>>(
        (const float4*)W_gat, (const float4*)W_ih, (const float4*)W_hh,
        (const float4*)lin_W,
        (uint2*)wgf, (uint2*)wihf, (uint2*)whhf, (uint2*)lwf);
    k_copy_split<<<B_NH4, 256>>>((const float4*)x_clique, (float4*)h, (uint2*)hf,
                                 as_, ad_, NH4);
    k_csr_zero<<<(N_NODES + 256) / 256, 256>>>(cnt);
    gemm_f16<<<dim3(HDIM / 128, MT), 256, GEMM_SMEM>>>(            // ts=0 xp GEMM
        hf, wgf, nullptr, nullptr, xpf, att_src, att_dst, as_, ad_,
        N_NODES, HDIM, HDIM);
    k_csr_hist<<<B_E, 256>>>(e_dst, cnt);
    k_csr_scan<<<1, 1024>>>(cnt, row, cur);
    k_csr_fill<<<B_E, 256>>>(e_src, e_dst, cur, srcs);

    for (int ts = 0; ts < TSTEPS; ++ts) {
        if (ts > 0)
            gemm_f16<<<dim3(HDIM / 128, MT), 256, GEMM_SMEM>>>(
                hf, wgf, nullptr, nullptr, xpf, att_src, att_dst, as_, ad_,
                N_NODES, HDIM, HDIM);
        k_node_ms<<<B_W, 256>>>(row, srcs, as_, ad_, mm, den);
        k_agg<<<N_NODES, 128>>>(row, srcs, as_, ad_, mm, den,
                                (const __half2*)xpf, gat_bias, (__half2*)gtf);
        gemm_f16_dual<<<dim3(H3 / 128, MT, 2), 256, GEMM_SMEM>>>(
            gtf, wihf, b_ih, gxf,
            hf, whhf, b_hh, ghf,
            N_NODES, H3, HDIM);
        k_gru<<<B_NH4, 256>>>((const uint2*)gxf, (const uint2*)ghf, (float4*)h,
                              (uint2*)hf, as_, ad_);
    }

    gemm_f16<<<dim3(OUT_DIM / 128, MT), 256, GEMM_SMEM>>>(
        hf, lwf, lin_b, out, nullptr, nullptr, nullptr, nullptr, nullptr,
        N_NODES, OUT_DIM, HDIM);
}